// round 5
// baseline (speedup 1.0000x reference)
#include <cuda_runtime.h>
#include <math.h>

// Problem geometry: N_LAYERS=12, H=12
//   Vq(L) = 2 + 13*L, Vm = Vq + 12, layer size = 37*Vq + 12
#define NP    32936      // P_TOTAL
#define NLM   32778      // _LM_BASE
#define NV    158        // V_TOTAL
#define NLAY  12

__constant__ int c_lbase[NLAY] = {0, 86, 653, 1701, 3230, 5240, 7731,
                                  10703, 14156, 18090, 22505, 27401};

__device__ __align__(16) float g_pp[NP];   // reparam prob per column
__device__ __align__(16) float g_rw[NP];   // 1/window per column

// ---------------------------------------------------------------------------
// Kernel 1: per-column sigmoid / window precompute (fp64 for canonical values)
// ---------------------------------------------------------------------------
__global__ void precompute_kernel(const float* __restrict__ sp) {
    int i = blockIdx.x * blockDim.x + threadIdx.x;
    if (i >= NP) return;
    double pd = 1.0 / (1.0 + exp(-(double)sp[i]));
    float p  = (float)pd;
    float w  = p * (1.0f - p);
    g_pp[i]  = w * p + (1.0f - w) * p;     // value == p up to 1 ulp (match ref formula)
    g_rw[i]  = __fdiv_rn(1.0f, w);
}

// ---------------------------------------------------------------------------
// Kernel 2: one block per batch row. Compute masks, prune dangling edges.
// ---------------------------------------------------------------------------
__global__ __launch_bounds__(256) void mask_kernel(const float* __restrict__ unif,
                                                   float* __restrict__ out) {
    __shared__ unsigned char pos[NP];   // 0/1 per edge (masks > 0)
    __shared__ unsigned char R[NV];     // forward reachability
    __shared__ unsigned char O[NV];     // backward (output) reachability
    __shared__ unsigned char anyrow[36];

    const int t    = threadIdx.x;
    const int warp = t >> 5;
    const int lane = t & 31;
    const size_t rowoff = (size_t)blockIdx.x * NP;

    const float4* u4  = (const float4*)(unif + rowoff);
    float4*       o4  = (float4*)(out + rowoff);
    const float4* pp4 = (const float4*)g_pp;
    const float4* rw4 = (const float4*)g_rw;
    float*        orow = out + rowoff;

    if (t < 2) R[t] = 1;   // input vertices always reachable

    // ---- Pass 1: stream unif, compute masks -> d_out, pos bits -> smem ----
    for (int i = t; i < NP / 4; i += 256) {
        float4 u = __ldcs(u4 + i);
        float4 p = pp4[i];
        float4 r = rw4[i];
        float x0 = (p.x - u.x) * r.x + 0.5f;
        float x1 = (p.y - u.y) * r.y + 0.5f;
        float x2 = (p.z - u.z) * r.z + 0.5f;
        float x3 = (p.w - u.w) * r.w + 0.5f;
        float4 m;
        m.x = fminf(fmaxf(x0, 0.0f), 1.0f);
        m.y = fminf(fmaxf(x1, 0.0f), 1.0f);
        m.z = fminf(fmaxf(x2, 0.0f), 1.0f);
        m.w = fminf(fmaxf(x3, 0.0f), 1.0f);
        __stcs(o4 + i, m);
        uchar4 pb;
        pb.x = (unsigned char)(x0 > 0.0f);
        pb.y = (unsigned char)(x1 > 0.0f);
        pb.z = (unsigned char)(x2 > 0.0f);
        pb.w = (unsigned char)(x3 > 0.0f);
        *(uchar4*)(pos + 4 * i) = pb;
    }
    __syncthreads();

    // ---- Forward reachability R ----
    for (int L = 0; L < NLAY; L++) {
        const int Vq = 2 + 13 * L;
        const int b  = c_lbase[L];
        // 36 qkv edge-rows: any(pos & R[:Vq]) per (c,h)
        for (int r = warp; r < 36; r += 8) {
            const unsigned char* prow = pos + b + r * Vq;
            int acc = 0;
            for (int j = lane; j < Vq; j += 32) acc |= (prow[j] & R[j]);
            int any = __any_sync(0xffffffffu, acc);
            if (lane == 0) anyrow[r] = (unsigned char)(any != 0);
        }
        __syncthreads();
        if (t < 12) R[Vq + t] = (unsigned char)(anyrow[t] & anyrow[12 + t] & anyrow[24 + t]);
        __syncthreads();
        // mlp row: any(mm & R[:Vm]) where R now includes this layer's heads
        if (warp == 0) {
            const int Vm = Vq + 12;
            const unsigned char* prow = pos + b + 36 * Vq;
            int acc = 0;
            for (int j = lane; j < Vm; j += 32) acc |= (prow[j] & R[j]);
            int any = __any_sync(0xffffffffu, acc);
            if (lane == 0) R[Vm] = (unsigned char)(any != 0);
        }
        __syncthreads();
    }

    // ---- Prune with keep(R): update pos in smem, zero killed outputs ----
    for (int L = 0; L < NLAY; L++) {
        const int Vq = 2 + 13 * L;
        const int b  = c_lbase[L];
        for (int r = warp; r < 37; r += 8) {
            int off, len;
            unsigned char hk;
            if (r < 36) {
                int h = (r >= 24) ? r - 24 : ((r >= 12) ? r - 12 : r);
                hk  = R[Vq + h];
                off = b + r * Vq;
                len = Vq;
            } else {
                hk  = R[Vq + 12];
                off = b + 36 * Vq;
                len = Vq + 12;
            }
            unsigned char* prow = pos + off;
            float*         outr = orow + off;
            for (int j = lane; j < len; j += 32) {
                if (prow[j] && !(hk && R[j])) { prow[j] = 0; outr[j] = 0.0f; }
            }
        }
    }
    // lm block: keep = R[j]
    if (t < NV) {
        if (pos[NLM + t] && !R[t]) { pos[NLM + t] = 0; orow[NLM + t] = 0.0f; }
    }
    __syncthreads();

    // ---- Backward reachability O (from pruned pos) ----
    if (t < NV) O[t] = pos[NLM + t];
    __syncthreads();
    for (int L = NLAY - 1; L >= 0; L--) {
        const int Vq = 2 + 13 * L;
        const int b  = c_lbase[L];
        const int Vm = Vq + 12;
        // mlp edges propagate O[mlp] down to inputs (incl. this layer's heads)
        if (t < Vm) O[t] |= (unsigned char)(pos[b + 36 * Vq + t] & O[Vm]);
        __syncthreads();
        // qkv edges propagate O[head] down to inputs
        if (t < Vq) {
            const unsigned char* pb = pos + b + t;
            unsigned char acc = 0;
#pragma unroll
            for (int r = 0; r < 36; r++) {
                acc |= (unsigned char)(pb[r * Vq] & O[Vq + (r % 12)]);
            }
            O[t] |= acc;
        }
        __syncthreads();
    }

    // ---- Final prune with keep(O): zero killed outputs ----
    for (int L = 0; L < NLAY; L++) {
        const int Vq = 2 + 13 * L;
        const int b  = c_lbase[L];
        for (int r = warp; r < 37; r += 8) {
            int off, len;
            unsigned char hk;
            if (r < 36) {
                int h = (r >= 24) ? r - 24 : ((r >= 12) ? r - 12 : r);
                hk  = O[Vq + h];
                off = b + r * Vq;
                len = Vq;
            } else {
                hk  = O[Vq + 12];
                off = b + 36 * Vq;
                len = Vq + 12;
            }
            const unsigned char* prow = pos + off;
            float*               outr = orow + off;
            for (int j = lane; j < len; j += 32) {
                if (prow[j] && !(hk && O[j])) outr[j] = 0.0f;
            }
        }
    }
    if (t < NV) {
        if (pos[NLM + t] && !O[t]) orow[NLM + t] = 0.0f;
    }
}

// ---------------------------------------------------------------------------
extern "C" void kernel_launch(void* const* d_in, const int* in_sizes, int n_in,
                              void* d_out, int out_size) {
    const float* sp   = (const float*)d_in[0];   // sample_params [NP]
    const float* unif = (const float*)d_in[1];   // unif [bz, NP]
    float*       out  = (float*)d_out;
    int bz = in_sizes[1] / NP;

    precompute_kernel<<<(NP + 255) / 256, 256>>>(sp);
    mask_kernel<<<bz, 256>>>(unif, out);
}

// round 6
// speedup vs baseline: 1.2413x; 1.2413x over previous
#include <cuda_runtime.h>
#include <math.h>

// Geometry: N_LAYERS=12, H=12, Vq(L)=2+13L, Vm=Vq+12, layer size 37*Vq+12
#define NP      32936     // P_TOTAL (elements == bits)
#define NLM     32778     // _LM_BASE
#define NV      158       // V_TOTAL
#define NLAY    12
#define NWORDS  1030      // ceil(NP/32)
#define NTHR    128

__constant__ int c_lbase[NLAY] = {0, 86, 653, 1701, 3230, 5240, 7731,
                                  10703, 14156, 18090, 22505, 27401};

__device__ __align__(16) float2 g_pr[NP];   // {reparam prob, 1/window}

// ---------------------------------------------------------------------------
__global__ void precompute_kernel(const float* __restrict__ sp) {
    int i = blockIdx.x * blockDim.x + threadIdx.x;
    if (i >= NP) return;
    double pd = 1.0 / (1.0 + exp(-(double)sp[i]));
    float p = (float)pd;
    float w = p * (1.0f - p);
    float pp = w * p + (1.0f - w) * p;     // value == p (match ref formula)
    g_pr[i] = make_float2(pp, __fdiv_rn(1.0f, w));
}

// ---------------------------------------------------------------------------
__device__ __forceinline__ unsigned ext32(const unsigned* P, int s) {
    return __funnelshift_r(P[s >> 5], P[(s >> 5) + 1], s & 31);
}
__device__ __forceinline__ unsigned lenmask(int n) {        // n in (0,32]
    return (n >= 32) ? 0xffffffffu : ((1u << n) - 1u);
}
__device__ __forceinline__ int getbit(const unsigned* B, int p) {
    return (B[p >> 5] >> (p & 31)) & 1;
}

// ---------------------------------------------------------------------------
__global__ __launch_bounds__(NTHR) void mask_kernel(const float* __restrict__ unif,
                                                    float* __restrict__ out) {
    __shared__ unsigned pos[NWORDS + 2];   // edge sign bits, +2 zero pad
    __shared__ unsigned sR[8];             // forward reachability bitset
    __shared__ unsigned sO[8];             // backward reachability bitset

    const int t = threadIdx.x, warp = t >> 5, lane = t & 31;
    const size_t rowoff = (size_t)blockIdx.x * NP;
    const float* urow = unif + rowoff;
    float*       orow = out + rowoff;

    if (t < 8) { sR[t] = (t == 0) ? 3u : 0u; sO[t] = 0u; }
    if (t == 0) { pos[NWORDS] = 0u; pos[NWORDS + 1] = 0u; }

    // ---- Pass 1: stream unif, write masks, build pos bitset via ballot ----
    for (int wi = warp; wi < NWORDS; wi += NTHR / 32) {
        int e = 32 * wi + lane;
        bool pb = false;
        if (e < NP) {
            float u = __ldcs(urow + e);
            float2 pr = __ldg(&g_pr[e]);
            float x = (pr.x - u) * pr.y + 0.5f;
            __stcs(orow + e, fminf(fmaxf(x, 0.0f), 1.0f));
            pb = x > 0.0f;
        }
        unsigned w = __ballot_sync(0xffffffffu, pb);
        if (lane == 0) pos[wi] = w;
    }
    __syncthreads();

    // ---- Forward reachability (warp 0, bit-parallel) ----
    if (warp == 0) {
        for (int L = 0; L < NLAY; L++) {
            const int Vq = 2 + 13 * L, b = c_lbase[L];
            // rows 0..31 on lanes, rows 32..35 on lanes 0..3
            unsigned acc1 = 0;
            {
                int s = b + lane * Vq;
                #pragma unroll
                for (int k = 0; k < 5; k++)
                    if (32 * k < Vq) acc1 |= ext32(pos, s + 32 * k) & sR[k];
            }
            bool a2 = false;
            if (lane < 4) {
                unsigned acc2 = 0;
                int s = b + (32 + lane) * Vq;
                #pragma unroll
                for (int k = 0; k < 5; k++)
                    if (32 * k < Vq) acc2 |= ext32(pos, s + 32 * k) & sR[k];
                a2 = acc2 != 0;
            }
            unsigned b1 = __ballot_sync(0xffffffffu, acc1 != 0);
            unsigned b2 = __ballot_sync(0xffffffffu, a2);
            if (lane == 0) {
                #pragma unroll
                for (int h = 0; h < 12; h++) {
                    unsigned q = (b1 >> h) & 1u;
                    unsigned kk = (b1 >> (12 + h)) & 1u;
                    unsigned v = (24 + h < 32) ? ((b1 >> (24 + h)) & 1u)
                                               : ((b2 >> (h - 8)) & 1u);
                    if (q & kk & v) { int p = Vq + h; sR[p >> 5] |= 1u << (p & 31); }
                }
            }
            __syncwarp();
            // mlp row (uses R including this layer's heads)
            const int Vm = Vq + 12, sm = b + 36 * Vq;
            bool am = false;
            if (lane < 5 && 32 * lane < Vm)
                am = (ext32(pos, sm + 32 * lane) & sR[lane]) != 0;
            unsigned bm = __ballot_sync(0xffffffffu, am);
            if (lane == 0 && bm) sR[Vm >> 5] |= 1u << (Vm & 31);
            __syncwarp();
        }
    }
    __syncthreads();

    // ---- R-prune: word-wise kill scan (kills are rare) ----
    for (int g = t; g < 444 + 5; g += NTHR) {
        if (g < 444) {
            int L = g / 37, r = g % 37;
            int Vq = 2 + 13 * L, b = c_lbase[L];
            int s, len, hv;
            if (r < 36) { s = b + r * Vq; len = Vq; hv = Vq + (r % 12); }
            else        { s = b + 36 * Vq; len = Vq + 12; hv = Vq + 12; }
            int hk = getbit(sR, hv);
            for (int k = 0; 32 * k < len; k++) {
                unsigned rowbits = ext32(pos, s + 32 * k);
                unsigned keep = hk ? sR[k] : 0u;
                unsigned kill = rowbits & ~keep & lenmask(len - 32 * k);
                while (kill) {
                    int bp = __ffs(kill) - 1; kill &= kill - 1;
                    int idx = s + 32 * k + bp;
                    orow[idx] = 0.0f;
                    atomicAnd(&pos[idx >> 5], ~(1u << (idx & 31)));
                }
            }
        } else {
            int k = g - 444;
            int s = NLM + 32 * k;
            unsigned kill = ext32(pos, s) & ~sR[k] & lenmask(NV - 32 * k);
            while (kill) {
                int bp = __ffs(kill) - 1; kill &= kill - 1;
                int idx = s + bp;
                orow[idx] = 0.0f;
                atomicAnd(&pos[idx >> 5], ~(1u << (idx & 31)));
            }
        }
    }
    __syncthreads();

    // ---- Backward reachability O (warp 0, bit-parallel) ----
    if (warp == 0) {
        if (lane < 5) sO[lane] = ext32(pos, NLM + 32 * lane) & lenmask(NV - 32 * lane);
        __syncwarp();
        for (int L = NLAY - 1; L >= 0; L--) {
            const int Vq = 2 + 13 * L, b = c_lbase[L], Vm = Vq + 12;
            int ob = getbit(sO, Vm);
            __syncwarp();
            if (ob && lane < 5 && 32 * lane < Vm)
                sO[lane] |= ext32(pos, b + 36 * Vq + 32 * lane) & lenmask(Vm - 32 * lane);
            __syncwarp();
            // qkv rows: OR row bits into O[:Vq] where head-O bit is set
            unsigned wk[5] = {0, 0, 0, 0, 0};
            {
                int hb = getbit(sO, Vq + (lane % 12));
                if (hb) {
                    int s = b + lane * Vq;
                    #pragma unroll
                    for (int k = 0; k < 5; k++)
                        if (32 * k < Vq) wk[k] = ext32(pos, s + 32 * k) & lenmask(Vq - 32 * k);
                }
            }
            if (lane < 4) {
                int hb = getbit(sO, Vq + ((32 + lane) % 12));
                if (hb) {
                    int s = b + (32 + lane) * Vq;
                    #pragma unroll
                    for (int k = 0; k < 5; k++)
                        if (32 * k < Vq) wk[k] |= ext32(pos, s + 32 * k) & lenmask(Vq - 32 * k);
                }
            }
            #pragma unroll
            for (int k = 0; k < 5; k++) {
                unsigned red = __reduce_or_sync(0xffffffffu, wk[k]);
                if (lane == 0) sO[k] |= red;
            }
            __syncwarp();
        }
    }
    __syncthreads();

    // ---- Final O-prune (zero-out only) ----
    for (int g = t; g < 444 + 5; g += NTHR) {
        if (g < 444) {
            int L = g / 37, r = g % 37;
            int Vq = 2 + 13 * L, b = c_lbase[L];
            int s, len, hv;
            if (r < 36) { s = b + r * Vq; len = Vq; hv = Vq + (r % 12); }
            else        { s = b + 36 * Vq; len = Vq + 12; hv = Vq + 12; }
            int hk = getbit(sO, hv);
            for (int k = 0; 32 * k < len; k++) {
                unsigned rowbits = ext32(pos, s + 32 * k);
                unsigned keep = hk ? sO[k] : 0u;
                unsigned kill = rowbits & ~keep & lenmask(len - 32 * k);
                while (kill) {
                    int bp = __ffs(kill) - 1; kill &= kill - 1;
                    orow[s + 32 * k + bp] = 0.0f;
                }
            }
        } else {
            int k = g - 444;
            int s = NLM + 32 * k;
            unsigned kill = ext32(pos, s) & ~sO[k] & lenmask(NV - 32 * k);
            while (kill) {
                int bp = __ffs(kill) - 1; kill &= kill - 1;
                orow[s + bp] = 0.0f;
            }
        }
    }
}

// ---------------------------------------------------------------------------
extern "C" void kernel_launch(void* const* d_in, const int* in_sizes, int n_in,
                              void* d_out, int out_size) {
    const float* sp   = (const float*)d_in[0];
    const float* unif = (const float*)d_in[1];
    float*       out  = (float*)d_out;
    int bz = in_sizes[1] / NP;

    precompute_kernel<<<(NP + 255) / 256, 256>>>(sp);
    mask_kernel<<<bz, NTHR>>>(unif, out);
}

// round 7
// speedup vs baseline: 1.9336x; 1.5578x over previous
#include <cuda_runtime.h>
#include <math.h>

// Geometry: N_LAYERS=12, H=12, Vq(L)=2+13L, Vm=Vq+12, layer size 37*Vq+12
#define NP      32936     // P_TOTAL
#define NLM     32778     // _LM_BASE
#define NV      158       // V_TOTAL
#define NLAY    12
#define NWORDS  1030      // ceil(NP/32)
#define NTHR    256
#define NCHUNK  258       // ceil(NP/128) 128-element chunks

__constant__ int c_lbase[NLAY] = {0, 86, 653, 1701, 3230, 5240, 7731,
                                  10703, 14156, 18090, 22505, 27401};

__device__ __align__(16) float g_pp[NP + 8];   // reparam prob
__device__ __align__(16) float g_rw[NP + 8];   // 1/window

// ---------------------------------------------------------------------------
__global__ void precompute_kernel(const float* __restrict__ sp) {
    int i = blockIdx.x * blockDim.x + threadIdx.x;
    if (i >= NP) return;
    double pd = 1.0 / (1.0 + exp(-(double)sp[i]));
    float p = (float)pd;
    float w = p * (1.0f - p);
    g_pp[i] = w * p + (1.0f - w) * p;     // value == p (matches ref formula)
    g_rw[i] = __fdiv_rn(1.0f, w);
}

// ---------------------------------------------------------------------------
__device__ __forceinline__ unsigned ext32(const unsigned* P, int s) {
    return __funnelshift_r(P[s >> 5], P[(s >> 5) + 1], s & 31);
}
__device__ __forceinline__ unsigned lenmask(int n) {        // n in (0,32]
    return (n >= 32) ? 0xffffffffu : ((1u << n) - 1u);
}
__device__ __forceinline__ int getbit(const unsigned* B, int p) {
    return (B[p >> 5] >> (p & 31)) & 1;
}
// spread low 8 bits to every 4th bit position (0,4,8,...,28)
__device__ __forceinline__ unsigned spread8(unsigned x) {
    x &= 0xFFu;
    x = (x | (x << 12)) & 0x000F000Fu;
    x = (x | (x << 6))  & 0x03030303u;
    x = (x | (x << 3))  & 0x11111111u;
    return x;
}

// ---------------------------------------------------------------------------
__global__ __launch_bounds__(NTHR, 6) void mask_kernel(const float* __restrict__ unif,
                                                       float* __restrict__ out) {
    __shared__ unsigned pos[NWORDS + 2];
    __shared__ unsigned sR[8];
    __shared__ unsigned sO[8];

    const int t = threadIdx.x, warp = t >> 5, lane = t & 31;
    const size_t rowoff = (size_t)blockIdx.x * NP;
    const float4* u4  = (const float4*)(unif + rowoff);
    float4*       o4  = (float4*)(out + rowoff);
    const float4* pp4 = (const float4*)g_pp;
    const float4* rw4 = (const float4*)g_rw;
    float*        orow = out + rowoff;

    if (t < 8) { sR[t] = (t == 0) ? 3u : 0u; sO[t] = 0u; }
    if (t == 0) { pos[NWORDS] = 0u; pos[NWORDS + 1] = 0u; }

    // ---- Pass 1: float4 stream; 4 ballots -> bit-transpose -> pos words ----
    for (int c = warp; c < NCHUNK; c += NTHR / 32) {
        int f = 32 * c + lane;            // float4 index
        bool inb = (4 * f) < NP;          // NP % 4 == 0
        bool p0 = false, p1 = false, p2 = false, p3 = false;
        if (inb) {
            float4 u = __ldcs(u4 + f);
            float4 p = __ldg(pp4 + f);
            float4 r = __ldg(rw4 + f);
            float x0 = (p.x - u.x) * r.x + 0.5f;
            float x1 = (p.y - u.y) * r.y + 0.5f;
            float x2 = (p.z - u.z) * r.z + 0.5f;
            float x3 = (p.w - u.w) * r.w + 0.5f;
            float4 m;
            m.x = fminf(fmaxf(x0, 0.0f), 1.0f);
            m.y = fminf(fmaxf(x1, 0.0f), 1.0f);
            m.z = fminf(fmaxf(x2, 0.0f), 1.0f);
            m.w = fminf(fmaxf(x3, 0.0f), 1.0f);
            __stcs(o4 + f, m);
            p0 = x0 > 0.0f; p1 = x1 > 0.0f; p2 = x2 > 0.0f; p3 = x3 > 0.0f;
        }
        unsigned b0 = __ballot_sync(0xffffffffu, p0);
        unsigned b1 = __ballot_sync(0xffffffffu, p1);
        unsigned b2 = __ballot_sync(0xffffffffu, p2);
        unsigned b3 = __ballot_sync(0xffffffffu, p3);
        if (lane < 4) {
            int sh = 8 * lane;
            unsigned w = spread8(b0 >> sh)
                       | (spread8(b1 >> sh) << 1)
                       | (spread8(b2 >> sh) << 2)
                       | (spread8(b3 >> sh) << 3);
            int wi = 4 * c + lane;
            if (wi < NWORDS) pos[wi] = w;
        }
    }
    __syncthreads();

    // ---- Forward reachability (warp 0, bit-parallel) ----
    if (warp == 0) {
        for (int L = 0; L < NLAY; L++) {
            const int Vq = 2 + 13 * L, b = c_lbase[L];
            unsigned acc1 = 0;
            {
                int s = b + lane * Vq;
                #pragma unroll
                for (int k = 0; k < 5; k++)
                    if (32 * k < Vq) acc1 |= ext32(pos, s + 32 * k) & sR[k];
            }
            bool a2 = false;
            if (lane < 4) {
                unsigned acc2 = 0;
                int s = b + (32 + lane) * Vq;
                #pragma unroll
                for (int k = 0; k < 5; k++)
                    if (32 * k < Vq) acc2 |= ext32(pos, s + 32 * k) & sR[k];
                a2 = acc2 != 0;
            }
            unsigned b1 = __ballot_sync(0xffffffffu, acc1 != 0);
            unsigned b2 = __ballot_sync(0xffffffffu, a2);
            if (lane == 0) {
                #pragma unroll
                for (int h = 0; h < 12; h++) {
                    unsigned q = (b1 >> h) & 1u;
                    unsigned kk = (b1 >> (12 + h)) & 1u;
                    unsigned v = (24 + h < 32) ? ((b1 >> (24 + h)) & 1u)
                                               : ((b2 >> (h - 8)) & 1u);
                    if (q & kk & v) { int p = Vq + h; sR[p >> 5] |= 1u << (p & 31); }
                }
            }
            __syncwarp();
            const int Vm = Vq + 12, sm = b + 36 * Vq;
            bool am = false;
            if (lane < 5 && 32 * lane < Vm)
                am = (ext32(pos, sm + 32 * lane) & sR[lane]) != 0;
            unsigned bm = __ballot_sync(0xffffffffu, am);
            if (lane == 0 && bm) sR[Vm >> 5] |= 1u << (Vm & 31);
            __syncwarp();
        }
    }
    __syncthreads();

    // ---- R-prune: word-wise kill scan (kills are rare) ----
    for (int g = t; g < 444 + 5; g += NTHR) {
        if (g < 444) {
            int L = g / 37, r = g % 37;
            int Vq = 2 + 13 * L, b = c_lbase[L];
            int s, len, hv;
            if (r < 36) { s = b + r * Vq; len = Vq; hv = Vq + (r % 12); }
            else        { s = b + 36 * Vq; len = Vq + 12; hv = Vq + 12; }
            int hk = getbit(sR, hv);
            for (int k = 0; 32 * k < len; k++) {
                unsigned rowbits = ext32(pos, s + 32 * k);
                unsigned keep = hk ? sR[k] : 0u;
                unsigned kill = rowbits & ~keep & lenmask(len - 32 * k);
                while (kill) {
                    int bp = __ffs(kill) - 1; kill &= kill - 1;
                    int idx = s + 32 * k + bp;
                    orow[idx] = 0.0f;
                    atomicAnd(&pos[idx >> 5], ~(1u << (idx & 31)));
                }
            }
        } else {
            int k = g - 444;
            int s = NLM + 32 * k;
            unsigned kill = ext32(pos, s) & ~sR[k] & lenmask(NV - 32 * k);
            while (kill) {
                int bp = __ffs(kill) - 1; kill &= kill - 1;
                int idx = s + bp;
                orow[idx] = 0.0f;
                atomicAnd(&pos[idx >> 5], ~(1u << (idx & 31)));
            }
        }
    }
    __syncthreads();

    // ---- Backward reachability O (warp 0, bit-parallel) ----
    if (warp == 0) {
        if (lane < 5) sO[lane] = ext32(pos, NLM + 32 * lane) & lenmask(NV - 32 * lane);
        __syncwarp();
        for (int L = NLAY - 1; L >= 0; L--) {
            const int Vq = 2 + 13 * L, b = c_lbase[L], Vm = Vq + 12;
            int ob = getbit(sO, Vm);
            __syncwarp();
            if (ob && lane < 5 && 32 * lane < Vm)
                sO[lane] |= ext32(pos, b + 36 * Vq + 32 * lane) & lenmask(Vm - 32 * lane);
            __syncwarp();
            unsigned wk[5] = {0, 0, 0, 0, 0};
            {
                int hb = getbit(sO, Vq + (lane % 12));
                if (hb) {
                    int s = b + lane * Vq;
                    #pragma unroll
                    for (int k = 0; k < 5; k++)
                        if (32 * k < Vq) wk[k] = ext32(pos, s + 32 * k) & lenmask(Vq - 32 * k);
                }
            }
            if (lane < 4) {
                int hb = getbit(sO, Vq + ((32 + lane) % 12));
                if (hb) {
                    int s = b + (32 + lane) * Vq;
                    #pragma unroll
                    for (int k = 0; k < 5; k++)
                        if (32 * k < Vq) wk[k] |= ext32(pos, s + 32 * k) & lenmask(Vq - 32 * k);
                }
            }
            #pragma unroll
            for (int k = 0; k < 5; k++) {
                unsigned red = __reduce_or_sync(0xffffffffu, wk[k]);
                if (lane == 0) sO[k] |= red;
            }
            __syncwarp();
        }
    }
    __syncthreads();

    // ---- Final O-prune (zero-out only) ----
    for (int g = t; g < 444 + 5; g += NTHR) {
        if (g < 444) {
            int L = g / 37, r = g % 37;
            int Vq = 2 + 13 * L, b = c_lbase[L];
            int s, len, hv;
            if (r < 36) { s = b + r * Vq; len = Vq; hv = Vq + (r % 12); }
            else        { s = b + 36 * Vq; len = Vq + 12; hv = Vq + 12; }
            int hk = getbit(sO, hv);
            for (int k = 0; 32 * k < len; k++) {
                unsigned rowbits = ext32(pos, s + 32 * k);
                unsigned keep = hk ? sO[k] : 0u;
                unsigned kill = rowbits & ~keep & lenmask(len - 32 * k);
                while (kill) {
                    int bp = __ffs(kill) - 1; kill &= kill - 1;
                    orow[s + 32 * k + bp] = 0.0f;
                }
            }
        } else {
            int k = g - 444;
            int s = NLM + 32 * k;
            unsigned kill = ext32(pos, s) & ~sO[k] & lenmask(NV - 32 * k);
            while (kill) {
                int bp = __ffs(kill) - 1; kill &= kill - 1;
                orow[s + bp] = 0.0f;
            }
        }
    }
}

// ---------------------------------------------------------------------------
extern "C" void kernel_launch(void* const* d_in, const int* in_sizes, int n_in,
                              void* d_out, int out_size) {
    const float* sp   = (const float*)d_in[0];
    const float* unif = (const float*)d_in[1];
    float*       out  = (float*)d_out;
    int bz = in_sizes[1] / NP;

    precompute_kernel<<<(NP + 255) / 256, 256>>>(sp);
    mask_kernel<<<bz, NTHR>>>(unif, out);
}

// round 8
// speedup vs baseline: 2.4354x; 1.2595x over previous
#include <cuda_runtime.h>
#include <math.h>

// Geometry: N_LAYERS=12, H=12, Vq(L)=2+13L, Vm=Vq+12, layer size 37*Vq+12
#define NP      32936     // P_TOTAL
#define NLM     32778     // _LM_BASE
#define NV      158       // V_TOTAL
#define NLAY    12
#define NWORDS  1030      // ceil(NP/32)
#define NTHR    256
#define NCHUNK  258       // ceil(NP/128)

__constant__ int c_lbase[NLAY] = {0, 86, 653, 1701, 3230, 5240, 7731,
                                  10703, 14156, 18090, 22505, 27401};

__device__ __align__(16) float g_pa[NP + 8];   // p*r + 0.5
__device__ __align__(16) float g_rw[NP + 8];   // 1/window

// ---------------------------------------------------------------------------
__global__ void precompute_kernel(const float* __restrict__ sp) {
    int i = blockIdx.x * blockDim.x + threadIdx.x;
    if (i >= NP) return;
    double pd = 1.0 / (1.0 + exp(-(double)sp[i]));
    float p = (float)pd;
    float w = p * (1.0f - p);
    float pp = w * p + (1.0f - w) * p;      // value == p (matches ref formula)
    float r  = __fdiv_rn(1.0f, w);
    g_rw[i] = r;
    g_pa[i] = fmaf(pp, r, 0.5f);            // A so that mask = sat(A - u*r)
}

// ---------------------------------------------------------------------------
__device__ __forceinline__ unsigned ext32(const unsigned* P, int s) {
    return __funnelshift_r(P[s >> 5], P[(s >> 5) + 1], s & 31);
}
__device__ __forceinline__ unsigned lenmask(int n) {        // n in (0,32]
    return (n >= 32) ? 0xffffffffu : ((1u << n) - 1u);
}
__device__ __forceinline__ int getbit(const unsigned* B, int p) {
    return (B[p >> 5] >> (p & 31)) & 1;
}
// spread low 8 bits to bit positions 0,4,8,...,28
__device__ __forceinline__ unsigned spread8(unsigned x) {
    x &= 0xFFu;
    x = (x | (x << 12)) & 0x000F000Fu;
    x = (x | (x << 6))  & 0x03030303u;
    x = (x | (x << 3))  & 0x11111111u;
    return x;
}

// ---------------------------------------------------------------------------
__global__ __launch_bounds__(NTHR, 8) void mask_kernel(const float* __restrict__ unif,
                                                       float* __restrict__ out) {
    __shared__ unsigned pos[NWORDS + 2];
    __shared__ unsigned sR[8];
    __shared__ unsigned sO[8];

    const int t = threadIdx.x, warp = t >> 5, lane = t & 31;
    const size_t rowoff = (size_t)blockIdx.x * NP;
    const float4* u4  = (const float4*)(unif + rowoff);
    float4*       o4  = (float4*)(out + rowoff);
    const float4* pa4 = (const float4*)g_pa;
    const float4* rw4 = (const float4*)g_rw;
    float*        orow = out + rowoff;

    if (t < 8) { sR[t] = (t == 0) ? 3u : 0u; sO[t] = 0u; }
    if (t == 0) { pos[NWORDS] = 0u; pos[NWORDS + 1] = 0u; }

    // ---- Pass 1: float4 stream; sat-FMA mask; ballots -> pos bitset ----
    for (int c = warp; c < NCHUNK; c += NTHR / 32) {
        int f = 32 * c + lane;
        bool p0 = false, p1 = false, p2 = false, p3 = false;
        if (4 * f < NP) {                         // NP % 4 == 0
            float4 u = __ldcs(u4 + f);
            float4 a = __ldg(pa4 + f);
            float4 r = __ldg(rw4 + f);
            float m0 = __saturatef(fmaf(-u.x, r.x, a.x));
            float m1 = __saturatef(fmaf(-u.y, r.y, a.y));
            float m2 = __saturatef(fmaf(-u.z, r.z, a.z));
            float m3 = __saturatef(fmaf(-u.w, r.w, a.w));
            float4 m = make_float4(m0, m1, m2, m3);
            __stcs(o4 + f, m);
            p0 = m0 > 0.0f; p1 = m1 > 0.0f; p2 = m2 > 0.0f; p3 = m3 > 0.0f;
        }
        unsigned b0 = __ballot_sync(0xffffffffu, p0);
        unsigned b1 = __ballot_sync(0xffffffffu, p1);
        unsigned b2 = __ballot_sync(0xffffffffu, p2);
        unsigned b3 = __ballot_sync(0xffffffffu, p3);
        if (lane < 4) {
            int sh = 8 * lane;
            unsigned w = spread8(b0 >> sh)
                       | (spread8(b1 >> sh) << 1)
                       | (spread8(b2 >> sh) << 2)
                       | (spread8(b3 >> sh) << 3);
            int wi = 4 * c + lane;
            if (wi < NWORDS) pos[wi] = w;
        }
    }
    __syncthreads();

    // ---- Forward reachability R (warp 0, bit-parallel, raw pos) ----
    if (warp == 0) {
        for (int L = 0; L < NLAY; L++) {
            const int Vq = 2 + 13 * L, b = c_lbase[L];
            unsigned acc1 = 0;
            {
                int s = b + lane * Vq;
                #pragma unroll
                for (int k = 0; k < 5; k++)
                    if (32 * k < Vq) acc1 |= ext32(pos, s + 32 * k) & sR[k];
            }
            bool a2 = false;
            if (lane < 4) {
                unsigned acc2 = 0;
                int s = b + (32 + lane) * Vq;
                #pragma unroll
                for (int k = 0; k < 5; k++)
                    if (32 * k < Vq) acc2 |= ext32(pos, s + 32 * k) & sR[k];
                a2 = acc2 != 0;
            }
            unsigned b1 = __ballot_sync(0xffffffffu, acc1 != 0);
            unsigned b2 = __ballot_sync(0xffffffffu, a2);
            if (lane == 0) {
                #pragma unroll
                for (int h = 0; h < 12; h++) {
                    unsigned q = (b1 >> h) & 1u;
                    unsigned kk = (b1 >> (12 + h)) & 1u;
                    unsigned v = (24 + h < 32) ? ((b1 >> (24 + h)) & 1u)
                                               : ((b2 >> (h - 8)) & 1u);
                    if (q & kk & v) { int p = Vq + h; sR[p >> 5] |= 1u << (p & 31); }
                }
            }
            __syncwarp();
            const int Vm = Vq + 12, sm = b + 36 * Vq;
            bool am = false;
            if (lane < 5 && 32 * lane < Vm)
                am = (ext32(pos, sm + 32 * lane) & sR[lane]) != 0;
            unsigned bm = __ballot_sync(0xffffffffu, am);
            if (lane == 0 && bm) sR[Vm >> 5] |= 1u << (Vm & 31);
            __syncwarp();
        }
    }
    __syncthreads();

    // ---- Backward reachability O on the R-pruned graph (keep(R) folded) ----
    if (warp == 0) {
        // O init = pos_lm & keepR_lm, keepR_lm[j] = R[j]
        if (lane < 5) sO[lane] = ext32(pos, NLM + 32 * lane) & sR[lane] & lenmask(NV - 32 * lane);
        __syncwarp();
        for (int L = NLAY - 1; L >= 0; L--) {
            const int Vq = 2 + 13 * L, b = c_lbase[L], Vm = Vq + 12;
            // mlp: O[:Vm] |= (pos & R[Vm] & R[:Vm]) & O[Vm]
            int obm = getbit(sO, Vm) & getbit(sR, Vm);
            __syncwarp();
            if (obm && lane < 5 && 32 * lane < Vm)
                sO[lane] |= ext32(pos, b + 36 * Vq + 32 * lane) & sR[lane] & lenmask(Vm - 32 * lane);
            __syncwarp();
            // qkv: O[:Vq] |= any_rows( (pos & R[h] & R[:Vq]) & O[h] )
            unsigned wk[5] = {0, 0, 0, 0, 0};
            {
                int h = Vq + (lane % 12);
                if (getbit(sR, h) & getbit(sO, h)) {
                    int s = b + lane * Vq;
                    #pragma unroll
                    for (int k = 0; k < 5; k++)
                        if (32 * k < Vq) wk[k] = ext32(pos, s + 32 * k) & sR[k] & lenmask(Vq - 32 * k);
                }
            }
            if (lane < 4) {
                int h = Vq + ((32 + lane) % 12);
                if (getbit(sR, h) & getbit(sO, h)) {
                    int s = b + (32 + lane) * Vq;
                    #pragma unroll
                    for (int k = 0; k < 5; k++)
                        if (32 * k < Vq) wk[k] |= ext32(pos, s + 32 * k) & sR[k] & lenmask(Vq - 32 * k);
                }
            }
            #pragma unroll
            for (int k = 0; k < 5; k++) {
                unsigned red = __reduce_or_sync(0xffffffffu, wk[k]);
                if (lane == 0) sO[k] |= red;
            }
            __syncwarp();
        }
    }
    __syncthreads();

    // ---- Single final prune: kill = pos & ~(keepR & keepO) ----
    for (int g = t; g < 444 + 5; g += NTHR) {
        if (g < 444) {
            int L = g / 37, r = g % 37;
            int Vq = 2 + 13 * L, b = c_lbase[L];
            int s, len, hv;
            if (r < 36) { s = b + r * Vq; len = Vq; hv = Vq + (r % 12); }
            else        { s = b + 36 * Vq; len = Vq + 12; hv = Vq + 12; }
            int hk = getbit(sR, hv) & getbit(sO, hv);
            for (int k = 0; 32 * k < len; k++) {
                unsigned keep = hk ? (sR[k] & sO[k]) : 0u;
                unsigned kill = ext32(pos, s + 32 * k) & ~keep & lenmask(len - 32 * k);
                while (kill) {
                    int bp = __ffs(kill) - 1; kill &= kill - 1;
                    orow[s + 32 * k + bp] = 0.0f;
                }
            }
        } else {
            int k = g - 444;
            int s = NLM + 32 * k;
            unsigned kill = ext32(pos, s) & ~(sR[k] & sO[k]) & lenmask(NV - 32 * k);
            while (kill) {
                int bp = __ffs(kill) - 1; kill &= kill - 1;
                orow[s + bp] = 0.0f;
            }
        }
    }
}

// ---------------------------------------------------------------------------
extern "C" void kernel_launch(void* const* d_in, const int* in_sizes, int n_in,
                              void* d_out, int out_size) {
    const float* sp   = (const float*)d_in[0];
    const float* unif = (const float*)d_in[1];
    float*       out  = (float*)d_out;
    int bz = in_sizes[1] / NP;

    precompute_kernel<<<(NP + 255) / 256, 256>>>(sp);
    mask_kernel<<<bz, NTHR>>>(unif, out);
}